// round 1
// baseline (speedup 1.0000x reference)
#include <cuda_runtime.h>

#define NHEADS 16
#define DH 64
#define SEQ 2048
#define BATCH 4
#define HDIM 1024
#define MTOT (BATCH*SEQ)

// Scratch for Q,K,V in [B,NH,S,D] layout (device globals: allocation-free).
__device__ float g_q[BATCH*NHEADS*SEQ*DH];
__device__ float g_k[BATCH*NHEADS*SEQ*DH];
__device__ float g_v[BATCH*NHEADS*SEQ*DH];

// ---------------------------------------------------------------------------
// Kernel 1: QKV projection (X @ W^T + b) with interleaved rotary on Q,K.
// Tiling: BM=64, BN=64, BK=16. 256 threads (16x16), each computes 4x4.
// blockIdx.z in {0,1,2} selects Q/K/V.
// ---------------------------------------------------------------------------
__global__ __launch_bounds__(256) void qkv_rope_kernel(
    const float* __restrict__ X,
    const float* __restrict__ Wq, const float* __restrict__ bq,
    const float* __restrict__ Wk, const float* __restrict__ bk,
    const float* __restrict__ Wv, const float* __restrict__ bv,
    const float* __restrict__ rel)
{
    __shared__ float As[16 * 68];
    __shared__ float Bs[16 * 68];

    const int z = blockIdx.z;
    const float* __restrict__ W    = (z == 0) ? Wq : (z == 1) ? Wk : Wv;
    const float* __restrict__ bias = (z == 0) ? bq : (z == 1) ? bk : bv;
    float* __restrict__ out        = (z == 0) ? g_q : (z == 1) ? g_k : g_v;

    const int n0 = blockIdx.x * 64;
    const int m0 = blockIdx.y * 64;
    const int t  = threadIdx.x;
    const int tx = t & 15;
    const int ty = t >> 4;
    const int lrow = t >> 2;          // 0..63
    const int lc4  = (t & 3) * 4;     // 0,4,8,12

    float acc[4][4] = {};

    for (int k0 = 0; k0 < HDIM; k0 += 16) {
        float4 av = *(const float4*)&X[(size_t)(m0 + lrow) * HDIM + k0 + lc4];
        float4 bv4 = *(const float4*)&W[(size_t)(n0 + lrow) * HDIM + k0 + lc4];
        __syncthreads();  // previous tile fully consumed
        As[(lc4 + 0) * 68 + lrow] = av.x;
        As[(lc4 + 1) * 68 + lrow] = av.y;
        As[(lc4 + 2) * 68 + lrow] = av.z;
        As[(lc4 + 3) * 68 + lrow] = av.w;
        Bs[(lc4 + 0) * 68 + lrow] = bv4.x;
        Bs[(lc4 + 1) * 68 + lrow] = bv4.y;
        Bs[(lc4 + 2) * 68 + lrow] = bv4.z;
        Bs[(lc4 + 3) * 68 + lrow] = bv4.w;
        __syncthreads();

        #pragma unroll
        for (int kk = 0; kk < 16; ++kk) {
            float4 a = *(const float4*)&As[kk * 68 + ty * 4];
            float4 b = *(const float4*)&Bs[kk * 68 + tx * 4];
            acc[0][0] += a.x * b.x; acc[0][1] += a.x * b.y; acc[0][2] += a.x * b.z; acc[0][3] += a.x * b.w;
            acc[1][0] += a.y * b.x; acc[1][1] += a.y * b.y; acc[1][2] += a.y * b.z; acc[1][3] += a.y * b.w;
            acc[2][0] += a.z * b.x; acc[2][1] += a.z * b.y; acc[2][2] += a.z * b.z; acc[2][3] += a.z * b.w;
            acc[3][0] += a.w * b.x; acc[3][1] += a.w * b.y; acc[3][2] += a.w * b.z; acc[3][3] += a.w * b.w;
        }
    }

    // Epilogue: bias + (optional) rotary, write to [B,NH,S,D] scratch.
    const int nb = n0 + tx * 4;       // column base; even, 4 consecutive cols
    const int h  = nb >> 6;           // all 4 cols same head (n0 % 64 == 0)
    const int db = nb & 63;           // even d base

    #pragma unroll
    for (int i = 0; i < 4; ++i) {
        const int m = m0 + ty * 4 + i;
        const int s = m & (SEQ - 1);
        const int bb = m >> 11;
        float o0 = acc[i][0] + bias[nb + 0];
        float o1 = acc[i][1] + bias[nb + 1];
        float o2 = acc[i][2] + bias[nb + 2];
        float o3 = acc[i][3] + bias[nb + 3];
        if (z < 2) {
            // pair (db, db+1): cos = rel[s, db+1], sin = rel[s, db]
            float c0 = rel[s * DH + db + 1];
            float s0 = rel[s * DH + db + 0];
            float c1 = rel[s * DH + db + 3];
            float s1 = rel[s * DH + db + 2];
            float e0 = o0 * c0 - o1 * s0;
            float e1 = o1 * c0 + o0 * s0;
            float e2 = o2 * c1 - o3 * s1;
            float e3 = o3 * c1 + o2 * s1;
            o0 = e0; o1 = e1; o2 = e2; o3 = e3;
        }
        float* dst = out + (((size_t)bb * NHEADS + h) * SEQ + s) * DH + db;
        dst[0] = o0; dst[1] = o1; dst[2] = o2; dst[3] = o3;
    }
}

// ---------------------------------------------------------------------------
// Kernel 2: flash attention. Br=Bc=64, 256 threads, fp32.
// Dynamic smem: Qt/Kt (d-major transposed), Vs (row-major), Pt (c-major).
// ---------------------------------------------------------------------------
__device__ __forceinline__ float redmax16(float v) {
    #pragma unroll
    for (int o = 8; o > 0; o >>= 1) v = fmaxf(v, __shfl_xor_sync(0xffffffffu, v, o));
    return v;
}
__device__ __forceinline__ float redsum16(float v) {
    #pragma unroll
    for (int o = 8; o > 0; o >>= 1) v += __shfl_xor_sync(0xffffffffu, v, o);
    return v;
}

#define ATT_SMEM (4 * 64 * 68 * 4)

__global__ __launch_bounds__(256) void attn_kernel(
    const float* __restrict__ mask, float* __restrict__ out)
{
    extern __shared__ float sm[];
    float* Qt = sm;                 // [64 d][68]
    float* Kt = sm + 64 * 68;       // [64 d][68]
    float* Vs = sm + 2 * 64 * 68;   // [64 c][68]
    float* Pt = sm + 3 * 64 * 68;   // [64 c][68]

    const int qt = blockIdx.x, h = blockIdx.y, b = blockIdx.z;
    const int t  = threadIdx.x;
    const int tx = t & 15, ty = t >> 4;

    const size_t bh = ((size_t)b * NHEADS + h) * SEQ;
    const float* __restrict__ qbase = g_q + bh * DH;
    const float* __restrict__ kbase = g_k + bh * DH;
    const float* __restrict__ vbase = g_v + bh * DH;
    const float* __restrict__ mrow  = mask + (size_t)b * SEQ;

    // Load Q tile transposed, pre-scaled by 1/sqrt(64)
    #pragma unroll
    for (int u = 0; u < 4; ++u) {
        int idx = t + u * 256;
        int r = idx >> 4;
        int d4 = (idx & 15) * 4;
        float4 qv = *(const float4*)&qbase[(size_t)(qt * 64 + r) * DH + d4];
        Qt[(d4 + 0) * 68 + r] = qv.x * 0.125f;
        Qt[(d4 + 1) * 68 + r] = qv.y * 0.125f;
        Qt[(d4 + 2) * 68 + r] = qv.z * 0.125f;
        Qt[(d4 + 3) * 68 + r] = qv.w * 0.125f;
    }

    float m_i[4], l_i[4], acc[4][4] = {};
    #pragma unroll
    for (int i = 0; i < 4; ++i) { m_i[i] = -1e30f; l_i[i] = 0.0f; }

    for (int kt = 0; kt < SEQ / 64; ++kt) {
        #pragma unroll
        for (int u = 0; u < 4; ++u) {
            int idx = t + u * 256;
            int r = idx >> 4;
            int d4 = (idx & 15) * 4;
            float4 kv = *(const float4*)&kbase[(size_t)(kt * 64 + r) * DH + d4];
            Kt[(d4 + 0) * 68 + r] = kv.x;
            Kt[(d4 + 1) * 68 + r] = kv.y;
            Kt[(d4 + 2) * 68 + r] = kv.z;
            Kt[(d4 + 3) * 68 + r] = kv.w;
            float4 vv = *(const float4*)&vbase[(size_t)(kt * 64 + r) * DH + d4];
            *(float4*)&Vs[r * 68 + d4] = vv;
        }
        __syncthreads();

        // S = Q K^T (Q pre-scaled)
        float sfr[4][4] = {};
        #pragma unroll 16
        for (int d = 0; d < 64; ++d) {
            float4 a = *(const float4*)&Qt[d * 68 + ty * 4];
            float4 bb = *(const float4*)&Kt[d * 68 + tx * 4];
            sfr[0][0] += a.x * bb.x; sfr[0][1] += a.x * bb.y; sfr[0][2] += a.x * bb.z; sfr[0][3] += a.x * bb.w;
            sfr[1][0] += a.y * bb.x; sfr[1][1] += a.y * bb.y; sfr[1][2] += a.y * bb.z; sfr[1][3] += a.y * bb.w;
            sfr[2][0] += a.z * bb.x; sfr[2][1] += a.z * bb.y; sfr[2][2] += a.z * bb.z; sfr[2][3] += a.z * bb.w;
            sfr[3][0] += a.w * bb.x; sfr[3][1] += a.w * bb.y; sfr[3][2] += a.w * bb.z; sfr[3][3] += a.w * bb.w;
        }
        // additive mask (per key column)
        float mk0 = mrow[kt * 64 + tx * 4 + 0];
        float mk1 = mrow[kt * 64 + tx * 4 + 1];
        float mk2 = mrow[kt * 64 + tx * 4 + 2];
        float mk3 = mrow[kt * 64 + tx * 4 + 3];
        #pragma unroll
        for (int i = 0; i < 4; ++i) {
            sfr[i][0] += mk0; sfr[i][1] += mk1; sfr[i][2] += mk2; sfr[i][3] += mk3;
        }

        // online softmax
        #pragma unroll
        for (int i = 0; i < 4; ++i) {
            float mloc = fmaxf(fmaxf(sfr[i][0], sfr[i][1]), fmaxf(sfr[i][2], sfr[i][3]));
            mloc = redmax16(mloc);
            float mnew = fmaxf(m_i[i], mloc);
            float corr = __expf(m_i[i] - mnew);
            float rs = 0.0f;
            #pragma unroll
            for (int j = 0; j < 4; ++j) {
                float p = __expf(sfr[i][j] - mnew);
                sfr[i][j] = p;
                rs += p;
            }
            rs = redsum16(rs);
            l_i[i] = l_i[i] * corr + rs;
            m_i[i] = mnew;
            acc[i][0] *= corr; acc[i][1] *= corr; acc[i][2] *= corr; acc[i][3] *= corr;
        }

        // stage P transposed: Pt[c][r]
        #pragma unroll
        for (int i = 0; i < 4; ++i)
            #pragma unroll
            for (int j = 0; j < 4; ++j)
                Pt[(tx * 4 + j) * 68 + ty * 4 + i] = sfr[i][j];
        __syncthreads();

        // acc += P @ V
        #pragma unroll 16
        for (int c = 0; c < 64; ++c) {
            float4 a = *(const float4*)&Pt[c * 68 + ty * 4];
            float4 bb = *(const float4*)&Vs[c * 68 + tx * 4];
            acc[0][0] += a.x * bb.x; acc[0][1] += a.x * bb.y; acc[0][2] += a.x * bb.z; acc[0][3] += a.x * bb.w;
            acc[1][0] += a.y * bb.x; acc[1][1] += a.y * bb.y; acc[1][2] += a.y * bb.z; acc[1][3] += a.y * bb.w;
            acc[2][0] += a.z * bb.x; acc[2][1] += a.z * bb.y; acc[2][2] += a.z * bb.z; acc[2][3] += a.z * bb.w;
            acc[3][0] += a.w * bb.x; acc[3][1] += a.w * bb.y; acc[3][2] += a.w * bb.z; acc[3][3] += a.w * bb.w;
        }
        __syncthreads();
    }

    // write out: [B,S,NH*D]
    #pragma unroll
    for (int i = 0; i < 4; ++i) {
        float inv = 1.0f / l_i[i];
        int r = qt * 64 + ty * 4 + i;
        float* dst = out + ((size_t)b * SEQ + r) * HDIM + h * DH + tx * 4;
        dst[0] = acc[i][0] * inv;
        dst[1] = acc[i][1] * inv;
        dst[2] = acc[i][2] * inv;
        dst[3] = acc[i][3] * inv;
    }
}

// ---------------------------------------------------------------------------
extern "C" void kernel_launch(void* const* d_in, const int* in_sizes, int n_in,
                              void* d_out, int out_size)
{
    const float* X    = (const float*)d_in[0];
    const float* mask = (const float*)d_in[1];
    const float* rel  = (const float*)d_in[2];
    const float* Wq   = (const float*)d_in[3];
    const float* bq   = (const float*)d_in[4];
    const float* Wk   = (const float*)d_in[5];
    const float* bk   = (const float*)d_in[6];
    const float* Wv   = (const float*)d_in[7];
    const float* bv   = (const float*)d_in[8];
    float* out = (float*)d_out;

    (void)in_sizes; (void)n_in; (void)out_size;

    dim3 g1(HDIM / 64, MTOT / 64, 3);
    qkv_rope_kernel<<<g1, 256>>>(X, Wq, bq, Wk, bk, Wv, bv, rel);

    cudaFuncSetAttribute(attn_kernel, cudaFuncAttributeMaxDynamicSharedMemorySize, ATT_SMEM);
    dim3 g2(SEQ / 64, NHEADS, BATCH);
    attn_kernel<<<g2, 256, ATT_SMEM>>>(mask, out);
}